// round 1
// baseline (speedup 1.0000x reference)
#include <cuda_runtime.h>
#include <math.h>

// Problem dims
#define Bsz 2
#define Sq  2048
#define Dm  1024
#define Hh  16
#define DHd 64
#define DRr 16
#define SDd 48
#define DCc 128
#define BS  (Bsz*Sq)   // 4096

// ---------------- device scratch (no allocs allowed) ----------------
__device__ float g_T1[(size_t)BS*512];        // [c_kv(128) | c_q(128) | k_rot_raw(256)]
__device__ float g_T2[(size_t)BS*2816];       // [k_up(768) | v(1024) | q_base(768) | q_rot(256)]
__device__ float g_Q[(size_t)Bsz*Hh*Sq*64];   // [b,h,s,d] (scale folded)
__device__ float g_K[(size_t)Bsz*Hh*Sq*64];
__device__ float g_V[(size_t)Bsz*Hh*Sq*64];
__device__ float g_O[(size_t)BS*1024];        // [b,s, h*64+d]
__device__ float g_Wc1[1024*512];
__device__ float g_bc1[512];
__device__ float g_Wc2[128*2816];
__device__ float g_bc2[2816];

// ---------------- weight packing ----------------
__global__ void pack1_kernel(const float* __restrict__ Wdkv, const float* __restrict__ bdkv,
                             const float* __restrict__ Wdq,  const float* __restrict__ bdq,
                             const float* __restrict__ Wkr,  const float* __restrict__ bkr) {
    int i = blockIdx.x * blockDim.x + threadIdx.x;
    if (i < 1024*512) {
        int k = i >> 9, n = i & 511;
        float v;
        if (n < 128)       v = Wdkv[k*128 + n];
        else if (n < 256)  v = Wdq [k*128 + (n-128)];
        else               v = Wkr [k*256 + (n-256)];
        g_Wc1[i] = v;
    }
    if (i < 512) {
        g_bc1[i] = (i < 128) ? bdkv[i] : (i < 256) ? bdq[i-128] : bkr[i-256];
    }
}

__global__ void pack2_kernel(const float* __restrict__ Wuk, const float* __restrict__ buk,
                             const float* __restrict__ Wuv, const float* __restrict__ buv,
                             const float* __restrict__ Wuq, const float* __restrict__ buq,
                             const float* __restrict__ Wqr, const float* __restrict__ bqr) {
    int i = blockIdx.x * blockDim.x + threadIdx.x;
    if (i < 128*2816) {
        int k = i / 2816, n = i % 2816;
        float v;
        if (n < 768)        v = Wuk[k*768  + n];
        else if (n < 1792)  v = Wuv[k*1024 + (n-768)];
        else if (n < 2560)  v = Wuq[k*768  + (n-1792)];
        else                v = Wqr[k*256  + (n-2560)];
        g_Wc2[i] = v;
    }
    if (i < 2816) {
        g_bc2[i] = (i < 768) ? buk[i] : (i < 1792) ? buv[i-768]
                 : (i < 2560) ? buq[i-1792] : bqr[i-2560];
    }
}

// ---------------- generic 128x128x8 SGEMM, 8x8 micro-tile ----------------
__global__ __launch_bounds__(256, 2)
void sgemm128(const float* __restrict__ A, int lda,
              const float* __restrict__ B, int ldb,
              const float* __restrict__ bias,
              float* __restrict__ C, int ldc, int K) {
    __shared__ float As[8][128];   // transposed [k][m]
    __shared__ float Bs[8][128];   // [k][n]
    const int tid = threadIdx.x;
    const int tx = tid & 15, ty = tid >> 4;
    const int row0 = blockIdx.y * 128, col0 = blockIdx.x * 128;

    const int arow = tid >> 1;
    const int acol = (tid & 1) * 4;
    const float* Ap = A + (size_t)(row0 + arow) * lda + acol;

    const int brow = tid >> 5;
    const int bcol = (tid & 31) * 4;
    const float* Bp = B + (size_t)brow * ldb + col0 + bcol;

    float acc[8][8];
#pragma unroll
    for (int i = 0; i < 8; i++)
#pragma unroll
        for (int j = 0; j < 8; j++) acc[i][j] = 0.0f;

    for (int k0 = 0; k0 < K; k0 += 8) {
        float4 a4 = *(const float4*)(Ap + k0);
        float4 b4 = *(const float4*)(Bp + (size_t)k0 * ldb);
        __syncthreads();
        As[acol+0][arow] = a4.x; As[acol+1][arow] = a4.y;
        As[acol+2][arow] = a4.z; As[acol+3][arow] = a4.w;
        *(float4*)&Bs[brow][bcol] = b4;
        __syncthreads();
#pragma unroll
        for (int k = 0; k < 8; k++) {
            float4 a0 = *(const float4*)&As[k][ty*8];
            float4 a1 = *(const float4*)&As[k][ty*8+4];
            float4 b0 = *(const float4*)&Bs[k][tx*8];
            float4 b1 = *(const float4*)&Bs[k][tx*8+4];
            float ar[8] = {a0.x,a0.y,a0.z,a0.w,a1.x,a1.y,a1.z,a1.w};
            float br[8] = {b0.x,b0.y,b0.z,b0.w,b1.x,b1.y,b1.z,b1.w};
#pragma unroll
            for (int i = 0; i < 8; i++)
#pragma unroll
                for (int j = 0; j < 8; j++)
                    acc[i][j] += ar[i] * br[j];
        }
    }

#pragma unroll
    for (int i = 0; i < 8; i++) {
        int r = row0 + ty*8 + i;
#pragma unroll
        for (int j = 0; j < 8; j += 4) {
            int c = col0 + tx*8 + j;
            float4 o;
            o.x = acc[i][j+0] + bias[c+0];
            o.y = acc[i][j+1] + bias[c+1];
            o.z = acc[i][j+2] + bias[c+2];
            o.w = acc[i][j+3] + bias[c+3];
            *(float4*)(C + (size_t)r * ldc + c) = o;
        }
    }
}

// ---------------- rope + layout assemble ----------------
__global__ void assemble_qkv(const float* __restrict__ T1, const float* __restrict__ T2,
                             float* __restrict__ Qg, float* __restrict__ Kg,
                             float* __restrict__ Vg) {
    int row = blockIdx.x;                  // 0..4095 = b*S + pos
    int b = row >> 11, pos = row & 2047;
    float t = (float)pos * (1.0f / 40.0f);
    const float* t2row = T2 + (size_t)row * 2816;
    const float* t1row = T1 + (size_t)row * 512;
#pragma unroll
    for (int it = 0; it < 4; it++) {
        int idx = threadIdx.x + (it << 8); // 0..1023  == h*64+d
        int h = idx >> 6, d = idx & 63;
        size_t oidx = ((size_t)(b*Hh + h) * Sq + pos) * 64 + d;
        Vg[oidx] = t2row[768 + idx];
        float qv, kv;
        if (d < 48) {
            qv = t2row[1792 + h*48 + d];
            kv = t2row[h*48 + d];
        } else {
            int j = d - 48;
            const float* xq = t2row + 2560 + h*16;
            const float* xk = t1row + 256  + h*16;
            if (j >= 8) { qv = xq[j]; kv = xk[j]; }
            else {
                int jj = j & 3;
                float ang = t * powf(10000.0f, -0.25f * (float)jj);
                float sn, cs; sincosf(ang, &sn, &cs);
                if (j < 4) { qv = xq[j]*cs - xq[j+4]*sn; kv = xk[j]*cs - xk[j+4]*sn; }
                else       { qv = xq[j]*cs + xq[j-4]*sn; kv = xk[j]*cs + xk[j-4]*sn; }
            }
        }
        Qg[oidx] = qv * 0.125f;   // fold 1/sqrt(DH)
        Kg[oidx] = kv;
    }
}

// ---------------- flash attention (64q x 64k tiles, d=64) ----------------
#define FLASH_SMEM_FLOATS (3*64*68 + 64*65)
__global__ __launch_bounds__(256)
void flash64(const float* __restrict__ Qg, const float* __restrict__ Kg,
             const float* __restrict__ Vg, float* __restrict__ Og) {
    extern __shared__ float sm[];
    float* Qs = sm;                 // [d][r], stride 68 (transposed)
    float* Ks = sm + 64*68;         // [d][c], stride 68 (transposed)
    float* Vs = sm + 2*64*68;       // [c][d], stride 68
    float* Ps = sm + 3*64*68;       // [r][c], stride 65

    const int tid = threadIdx.x;
    const int tx = tid & 15, ty = tid >> 4;
    const int qb = blockIdx.x, h = blockIdx.y, b = blockIdx.z;
    const size_t base = ((size_t)(b*Hh + h)) * Sq * 64;
    const float* Qp = Qg + base + (size_t)qb * 64 * 64;

#pragma unroll
    for (int t = 0; t < 4; t++) {
        int e = tid + t*256;
        int r = e >> 4, d = (e & 15) << 2;
        float4 v = *(const float4*)(Qp + r*64 + d);
        Qs[(d+0)*68 + r] = v.x; Qs[(d+1)*68 + r] = v.y;
        Qs[(d+2)*68 + r] = v.z; Qs[(d+3)*68 + r] = v.w;
    }

    float m[4], l[4], o[4][4];
#pragma unroll
    for (int i = 0; i < 4; i++) {
        m[i] = -1e30f; l[i] = 0.0f;
#pragma unroll
        for (int j = 0; j < 4; j++) o[i][j] = 0.0f;
    }

    for (int kt = 0; kt < Sq; kt += 64) {
        __syncthreads();   // prev-iter smem reads complete
        const float* Kp = Kg + base + (size_t)kt * 64;
        const float* Vp = Vg + base + (size_t)kt * 64;
#pragma unroll
        for (int t = 0; t < 4; t++) {
            int e = tid + t*256;
            int r = e >> 4, d = (e & 15) << 2;
            float4 kv = *(const float4*)(Kp + r*64 + d);
            Ks[(d+0)*68 + r] = kv.x; Ks[(d+1)*68 + r] = kv.y;
            Ks[(d+2)*68 + r] = kv.z; Ks[(d+3)*68 + r] = kv.w;
            float4 vv = *(const float4*)(Vp + r*64 + d);
            *(float4*)&Vs[r*68 + d] = vv;
        }
        __syncthreads();

        float s[4][4];
#pragma unroll
        for (int i = 0; i < 4; i++)
#pragma unroll
            for (int j = 0; j < 4; j++) s[i][j] = 0.0f;

#pragma unroll 8
        for (int k = 0; k < 64; k++) {
            float4 a  = *(const float4*)&Qs[k*68 + (ty<<2)];
            float4 bb = *(const float4*)&Ks[k*68 + (tx<<2)];
            float ar[4] = {a.x,a.y,a.z,a.w};
            float br[4] = {bb.x,bb.y,bb.z,bb.w};
#pragma unroll
            for (int i = 0; i < 4; i++)
#pragma unroll
                for (int j = 0; j < 4; j++)
                    s[i][j] += ar[i] * br[j];
        }

#pragma unroll
        for (int i = 0; i < 4; i++) {
            float tm = fmaxf(fmaxf(s[i][0], s[i][1]), fmaxf(s[i][2], s[i][3]));
            tm = fmaxf(tm, __shfl_xor_sync(0xffffffffu, tm, 1));
            tm = fmaxf(tm, __shfl_xor_sync(0xffffffffu, tm, 2));
            tm = fmaxf(tm, __shfl_xor_sync(0xffffffffu, tm, 4));
            tm = fmaxf(tm, __shfl_xor_sync(0xffffffffu, tm, 8));
            float mn = fmaxf(m[i], tm);
            float sum = 0.0f;
#pragma unroll
            for (int j = 0; j < 4; j++) {
                s[i][j] = __expf(s[i][j] - mn);
                sum += s[i][j];
            }
            sum += __shfl_xor_sync(0xffffffffu, sum, 1);
            sum += __shfl_xor_sync(0xffffffffu, sum, 2);
            sum += __shfl_xor_sync(0xffffffffu, sum, 4);
            sum += __shfl_xor_sync(0xffffffffu, sum, 8);
            float al = __expf(m[i] - mn);
            l[i] = l[i] * al + sum;
            m[i] = mn;
#pragma unroll
            for (int j = 0; j < 4; j++) {
                o[i][j] *= al;
                Ps[((ty<<2)+i)*65 + (tx<<2)+j] = s[i][j];
            }
        }
        __syncthreads();

#pragma unroll 8
        for (int c = 0; c < 64; c++) {
            float p0 = Ps[((ty<<2)+0)*65 + c];
            float p1 = Ps[((ty<<2)+1)*65 + c];
            float p2 = Ps[((ty<<2)+2)*65 + c];
            float p3 = Ps[((ty<<2)+3)*65 + c];
            float4 vv = *(const float4*)&Vs[c*68 + (tx<<2)];
            o[0][0] += p0*vv.x; o[0][1] += p0*vv.y; o[0][2] += p0*vv.z; o[0][3] += p0*vv.w;
            o[1][0] += p1*vv.x; o[1][1] += p1*vv.y; o[1][2] += p1*vv.z; o[1][3] += p1*vv.w;
            o[2][0] += p2*vv.x; o[2][1] += p2*vv.y; o[2][2] += p2*vv.z; o[2][3] += p2*vv.w;
            o[3][0] += p3*vv.x; o[3][1] += p3*vv.y; o[3][2] += p3*vv.z; o[3][3] += p3*vv.w;
        }
    }

#pragma unroll
    for (int i = 0; i < 4; i++) {
        float inv = 1.0f / l[i];
        int srow = qb*64 + (ty<<2) + i;
        float4 out4 = make_float4(o[i][0]*inv, o[i][1]*inv, o[i][2]*inv, o[i][3]*inv);
        *(float4*)(Og + ((size_t)b*Sq + srow)*1024 + h*64 + (tx<<2)) = out4;
    }
}

// ---------------- launch ----------------
extern "C" void kernel_launch(void* const* d_in, const int* in_sizes, int n_in,
                              void* d_out, int out_size) {
    (void)in_sizes; (void)n_in; (void)out_size;
    const float* h    = (const float*)d_in[0];
    const float* Wdkv = (const float*)d_in[1];
    const float* bdkv = (const float*)d_in[2];
    const float* Wdq  = (const float*)d_in[3];
    const float* bdq  = (const float*)d_in[4];
    const float* Wuk  = (const float*)d_in[5];
    const float* buk  = (const float*)d_in[6];
    const float* Wuv  = (const float*)d_in[7];
    const float* buv  = (const float*)d_in[8];
    const float* Wuq  = (const float*)d_in[9];
    const float* buq  = (const float*)d_in[10];
    const float* Wqr  = (const float*)d_in[11];
    const float* bqr  = (const float*)d_in[12];
    const float* Wkr  = (const float*)d_in[13];
    const float* bkr  = (const float*)d_in[14];
    const float* Wo   = (const float*)d_in[15];
    const float* bo   = (const float*)d_in[16];
    float* out = (float*)d_out;

    float *T1, *T2, *Q, *K, *V, *O, *Wc1, *bc1, *Wc2, *bc2;
    cudaGetSymbolAddress((void**)&T1,  g_T1);
    cudaGetSymbolAddress((void**)&T2,  g_T2);
    cudaGetSymbolAddress((void**)&Q,   g_Q);
    cudaGetSymbolAddress((void**)&K,   g_K);
    cudaGetSymbolAddress((void**)&V,   g_V);
    cudaGetSymbolAddress((void**)&O,   g_O);
    cudaGetSymbolAddress((void**)&Wc1, g_Wc1);
    cudaGetSymbolAddress((void**)&bc1, g_bc1);
    cudaGetSymbolAddress((void**)&Wc2, g_Wc2);
    cudaGetSymbolAddress((void**)&bc2, g_bc2);

    static int smem_set = 0;
    if (!smem_set) {
        cudaFuncSetAttribute(flash64, cudaFuncAttributeMaxDynamicSharedMemorySize,
                             FLASH_SMEM_FLOATS * (int)sizeof(float));
        smem_set = 1;
    }

    // 1) pack weights
    pack1_kernel<<<(1024*512 + 255)/256, 256>>>(Wdkv, bdkv, Wdq, bdq, Wkr, bkr);
    pack2_kernel<<<(128*2816 + 255)/256, 256>>>(Wuk, buk, Wuv, buv, Wuq, buq, Wqr, bqr);

    // 2) down-proj + k_rot raw: [4096,1024] @ [1024,512] -> T1
    sgemm128<<<dim3(512/128, BS/128), 256>>>(h, Dm, Wc1, 512, bc1, T1, 512, Dm);

    // 3) up-projections (K=128)
    //    c_kv @ [Wuk|Wuv] -> T2[:, 0:1792]
    sgemm128<<<dim3(1792/128, BS/128), 256>>>(T1, 512, Wc2, 2816, bc2, T2, 2816, 128);
    //    c_q @ [Wuq|Wqr]  -> T2[:, 1792:2816]
    sgemm128<<<dim3(1024/128, BS/128), 256>>>(T1 + 128, 512, Wc2 + 1792, 2816,
                                              bc2 + 1792, T2 + 1792, 2816, 128);

    // 4) rope + layout
    assemble_qkv<<<BS, 256>>>(T1, T2, Q, K, V);

    // 5) attention
    flash64<<<dim3(Sq/64, Hh, Bsz), 256, FLASH_SMEM_FLOATS * sizeof(float)>>>(Q, K, V, O);

    // 6) output projection: [4096,1024] @ [1024,1024] + b_o -> out
    sgemm128<<<dim3(1024/128, BS/128), 256>>>(O, 1024, Wo, 1024, bo, out, 1024, Dm);
}

// round 2
// speedup vs baseline: 1.6554x; 1.6554x over previous
#include <cuda_runtime.h>
#include <math.h>

// Problem dims
#define Bsz 2
#define Sq  2048
#define Dm  1024
#define Hh  16
#define DHd 64
#define DRr 16
#define SDd 48
#define DCc 128
#define BS  (Bsz*Sq)   // 4096

// ---------------- device scratch (no allocs allowed) ----------------
__device__ float g_T1[(size_t)BS*512];        // [c_kv(128) | c_q(128) | k_rot_raw(256)]
__device__ float g_T2[(size_t)BS*2816];       // [k_up(768) | v(1024) | q_base(768) | q_rot(256)]
__device__ float g_Q[(size_t)Bsz*Hh*Sq*64];   // [b,h,s,d] (scale folded, tf32-rounded)
__device__ float g_K[(size_t)Bsz*Hh*Sq*64];   // tf32-rounded
__device__ float g_V[(size_t)Bsz*Hh*Sq*64];   // tf32-rounded
__device__ float g_O[(size_t)BS*1024];        // [b,s, h*64+d]
__device__ float g_Wc1[1024*512];
__device__ float g_bc1[512];
__device__ float g_Wc2[128*2816];
__device__ float g_bc2[2816];

__device__ __forceinline__ float to_tf32(float x) {
    float r;
    asm("cvt.rna.tf32.f32 %0, %1;" : "=f"(r) : "f"(x));
    return r;
}

__device__ __forceinline__ void mma_tf32(float c[4], const unsigned a[4], const unsigned b[2]) {
    asm volatile(
        "mma.sync.aligned.m16n8k8.row.col.f32.tf32.tf32.f32 "
        "{%0,%1,%2,%3}, {%4,%5,%6,%7}, {%8,%9}, {%0,%1,%2,%3};"
        : "+f"(c[0]), "+f"(c[1]), "+f"(c[2]), "+f"(c[3])
        : "r"(a[0]), "r"(a[1]), "r"(a[2]), "r"(a[3]), "r"(b[0]), "r"(b[1]));
}

// ---------------- weight packing ----------------
__global__ void pack1_kernel(const float* __restrict__ Wdkv, const float* __restrict__ bdkv,
                             const float* __restrict__ Wdq,  const float* __restrict__ bdq,
                             const float* __restrict__ Wkr,  const float* __restrict__ bkr) {
    int i = blockIdx.x * blockDim.x + threadIdx.x;
    if (i < 1024*512) {
        int k = i >> 9, n = i & 511;
        float v;
        if (n < 128)       v = Wdkv[k*128 + n];
        else if (n < 256)  v = Wdq [k*128 + (n-128)];
        else               v = Wkr [k*256 + (n-256)];
        g_Wc1[i] = v;
    }
    if (i < 512) {
        g_bc1[i] = (i < 128) ? bdkv[i] : (i < 256) ? bdq[i-128] : bkr[i-256];
    }
}

__global__ void pack2_kernel(const float* __restrict__ Wuk, const float* __restrict__ buk,
                             const float* __restrict__ Wuv, const float* __restrict__ buv,
                             const float* __restrict__ Wuq, const float* __restrict__ buq,
                             const float* __restrict__ Wqr, const float* __restrict__ bqr) {
    int i = blockIdx.x * blockDim.x + threadIdx.x;
    if (i < 128*2816) {
        int k = i / 2816, n = i % 2816;
        float v;
        if (n < 768)        v = Wuk[k*768  + n];
        else if (n < 1792)  v = Wuv[k*1024 + (n-768)];
        else if (n < 2560)  v = Wuq[k*768  + (n-1792)];
        else                v = Wqr[k*256  + (n-2560)];
        g_Wc2[i] = v;
    }
    if (i < 2816) {
        g_bc2[i] = (i < 768) ? buk[i] : (i < 1792) ? buv[i-768]
                 : (i < 2560) ? buq[i-1792] : bqr[i-2560];
    }
}

// ---------------- generic 128x128x8 SGEMM, 8x8 micro-tile (fp32 exact) ----------------
__global__ __launch_bounds__(256, 2)
void sgemm128(const float* __restrict__ A, int lda,
              const float* __restrict__ B, int ldb,
              const float* __restrict__ bias,
              float* __restrict__ C, int ldc, int K) {
    __shared__ float As[8][128];
    __shared__ float Bs[8][128];
    const int tid = threadIdx.x;
    const int tx = tid & 15, ty = tid >> 4;
    const int row0 = blockIdx.y * 128, col0 = blockIdx.x * 128;

    const int arow = tid >> 1;
    const int acol = (tid & 1) * 4;
    const float* Ap = A + (size_t)(row0 + arow) * lda + acol;

    const int brow = tid >> 5;
    const int bcol = (tid & 31) * 4;
    const float* Bp = B + (size_t)brow * ldb + col0 + bcol;

    float acc[8][8];
#pragma unroll
    for (int i = 0; i < 8; i++)
#pragma unroll
        for (int j = 0; j < 8; j++) acc[i][j] = 0.0f;

    for (int k0 = 0; k0 < K; k0 += 8) {
        float4 a4 = *(const float4*)(Ap + k0);
        float4 b4 = *(const float4*)(Bp + (size_t)k0 * ldb);
        __syncthreads();
        As[acol+0][arow] = a4.x; As[acol+1][arow] = a4.y;
        As[acol+2][arow] = a4.z; As[acol+3][arow] = a4.w;
        *(float4*)&Bs[brow][bcol] = b4;
        __syncthreads();
#pragma unroll
        for (int k = 0; k < 8; k++) {
            float4 a0 = *(const float4*)&As[k][ty*8];
            float4 a1 = *(const float4*)&As[k][ty*8+4];
            float4 b0 = *(const float4*)&Bs[k][tx*8];
            float4 b1 = *(const float4*)&Bs[k][tx*8+4];
            float ar[8] = {a0.x,a0.y,a0.z,a0.w,a1.x,a1.y,a1.z,a1.w};
            float br[8] = {b0.x,b0.y,b0.z,b0.w,b1.x,b1.y,b1.z,b1.w};
#pragma unroll
            for (int i = 0; i < 8; i++)
#pragma unroll
                for (int j = 0; j < 8; j++)
                    acc[i][j] += ar[i] * br[j];
        }
    }

#pragma unroll
    for (int i = 0; i < 8; i++) {
        int r = row0 + ty*8 + i;
#pragma unroll
        for (int j = 0; j < 8; j += 4) {
            int c = col0 + tx*8 + j;
            float4 o;
            o.x = acc[i][j+0] + bias[c+0];
            o.y = acc[i][j+1] + bias[c+1];
            o.z = acc[i][j+2] + bias[c+2];
            o.w = acc[i][j+3] + bias[c+3];
            *(float4*)(C + (size_t)r * ldc + c) = o;
        }
    }
}

// ---------------- rope + layout assemble (tf32-round Q,K,V) ----------------
__global__ void assemble_qkv(const float* __restrict__ T1, const float* __restrict__ T2,
                             float* __restrict__ Qg, float* __restrict__ Kg,
                             float* __restrict__ Vg) {
    int row = blockIdx.x;                  // 0..4095 = b*S + pos
    int b = row >> 11, pos = row & 2047;
    float t = (float)pos * (1.0f / 40.0f);
    const float* t2row = T2 + (size_t)row * 2816;
    const float* t1row = T1 + (size_t)row * 512;
#pragma unroll
    for (int it = 0; it < 4; it++) {
        int idx = threadIdx.x + (it << 8); // 0..1023  == h*64+d
        int h = idx >> 6, d = idx & 63;
        size_t oidx = ((size_t)(b*Hh + h) * Sq + pos) * 64 + d;
        Vg[oidx] = to_tf32(t2row[768 + idx]);
        float qv, kv;
        if (d < 48) {
            qv = t2row[1792 + h*48 + d];
            kv = t2row[h*48 + d];
        } else {
            int j = d - 48;
            const float* xq = t2row + 2560 + h*16;
            const float* xk = t1row + 256  + h*16;
            if (j >= 8) { qv = xq[j]; kv = xk[j]; }
            else {
                int jj = j & 3;
                float ang = t * powf(10000.0f, -0.25f * (float)jj);
                float sn, cs; sincosf(ang, &sn, &cs);
                if (j < 4) { qv = xq[j]*cs - xq[j+4]*sn; kv = xk[j]*cs - xk[j+4]*sn; }
                else       { qv = xq[j]*cs + xq[j-4]*sn; kv = xk[j]*cs + xk[j-4]*sn; }
            }
        }
        Qg[oidx] = to_tf32(qv * 0.125f);   // fold 1/sqrt(DH)
        Kg[oidx] = to_tf32(kv);
    }
}

// ---------------- flash attention, tf32 mma.sync (128q x 64k tiles, d=64) ----------------
// 8 warps: warp w -> rows 32*(w&3), cols 32*(w>>2) of the 128x64 S tile.
// smem: Ps[128][68] (Q staging, then P), Ks[64][68] natural, Vs[64][68] transposed,
//       Red[512] (rowmax [r*2+cw] at 0, rowsum at 256).
#define FPAD 68
#define FLASH_SMEM_FLOATS (128*FPAD + 64*FPAD + 64*FPAD + 512)
__global__ __launch_bounds__(256, 1)
void flash_tf32(const float* __restrict__ Qg, const float* __restrict__ Kg,
                const float* __restrict__ Vg, float* __restrict__ Og) {
    extern __shared__ float sm[];
    float* Ps  = sm;
    float* Ks  = sm + 128*FPAD;
    float* Vs  = Ks + 64*FPAD;
    float* Red = Vs + 64*FPAD;

    const int tid  = threadIdx.x;
    const int lane = tid & 31;
    const int w    = tid >> 5;
    const int rw   = w & 3;        // row group: rows 32*rw .. +31
    const int cw   = w >> 2;       // col group: cols 32*cw .. +31
    const int g    = lane >> 2;    // 0..7
    const int q4   = lane & 3;     // 0..3

    const int qb = blockIdx.x, h = blockIdx.y, b = blockIdx.z;
    const size_t base = ((size_t)(b*Hh + h)) * Sq * 64;
    const float* Qp = Qg + base + (size_t)qb * 128 * 64;

    // stage Q tile (128x64) into Ps
#pragma unroll
    for (int t = 0; t < 8; t++) {
        int idx = tid + t*256;
        int r = idx >> 4, c = (idx & 15) << 2;
        *(float4*)&Ps[r*FPAD + c] = *(const float4*)(Qp + r*64 + c);
    }
    __syncthreads();

    // Q A-fragments in registers: qa[kstep][mtile][4]
    unsigned qa[8][2][4];
#pragma unroll
    for (int s = 0; s < 8; s++)
#pragma unroll
        for (int mt = 0; mt < 2; mt++) {
            int row = rw*32 + mt*16 + g;
            int col = s*8 + q4;
            qa[s][mt][0] = __float_as_uint(Ps[row*FPAD + col]);
            qa[s][mt][1] = __float_as_uint(Ps[(row+8)*FPAD + col]);
            qa[s][mt][2] = __float_as_uint(Ps[row*FPAD + col + 4]);
            qa[s][mt][3] = __float_as_uint(Ps[(row+8)*FPAD + col + 4]);
        }

    float mrun[2][2], lrun[2][2], o[2][4][4];
#pragma unroll
    for (int mt = 0; mt < 2; mt++)
#pragma unroll
        for (int i = 0; i < 2; i++) { mrun[mt][i] = -1e30f; lrun[mt][i] = 0.0f; }
#pragma unroll
    for (int mt = 0; mt < 2; mt++)
#pragma unroll
        for (int nt = 0; nt < 4; nt++)
#pragma unroll
            for (int c = 0; c < 4; c++) o[mt][nt][c] = 0.0f;

    for (int kt = 0; kt < Sq; kt += 64) {
        __syncthreads();   // previous PV reads of Ks/Vs/Ps done
        const float* Kp = Kg + base + (size_t)kt * 64;
        const float* Vp = Vg + base + (size_t)kt * 64;
#pragma unroll
        for (int t = 0; t < 4; t++) {
            int idx = tid + t*256;
            int r = idx >> 4, c = (idx & 15) << 2;
            float4 kv = *(const float4*)(Kp + r*64 + c);
            *(float4*)&Ks[r*FPAD + c] = kv;               // natural [kcol][d]
            float4 vv = *(const float4*)(Vp + r*64 + c);
            Vs[(c+0)*FPAD + r] = vv.x;                    // transposed [d][kcol]
            Vs[(c+1)*FPAD + r] = vv.y;
            Vs[(c+2)*FPAD + r] = vv.z;
            Vs[(c+3)*FPAD + r] = vv.w;
        }
        __syncthreads();

        // ---- S = Q @ K^T, warp tile 32x32 ----
        float sfr[2][4][4];
#pragma unroll
        for (int mt = 0; mt < 2; mt++)
#pragma unroll
            for (int nt = 0; nt < 4; nt++)
#pragma unroll
                for (int c = 0; c < 4; c++) sfr[mt][nt][c] = 0.0f;

#pragma unroll
        for (int s = 0; s < 8; s++) {
            unsigned bf[4][2];
#pragma unroll
            for (int nt = 0; nt < 4; nt++) {
                int col0 = cw*32 + nt*8 + g;
                bf[nt][0] = __float_as_uint(Ks[col0*FPAD + s*8 + q4]);
                bf[nt][1] = __float_as_uint(Ks[col0*FPAD + s*8 + 4 + q4]);
            }
#pragma unroll
            for (int mt = 0; mt < 2; mt++)
#pragma unroll
                for (int nt = 0; nt < 4; nt++)
                    mma_tf32(sfr[mt][nt], qa[s][mt], bf[nt]);
        }

        // ---- row max (warp-local 32 cols), publish per (row, cw) ----
#pragma unroll
        for (int mt = 0; mt < 2; mt++)
#pragma unroll
            for (int i = 0; i < 2; i++) {
                int r = rw*32 + mt*16 + i*8 + g;
                float mx = -1e30f;
#pragma unroll
                for (int nt = 0; nt < 4; nt++)
                    mx = fmaxf(mx, fmaxf(sfr[mt][nt][2*i], sfr[mt][nt][2*i+1]));
                mx = fmaxf(mx, __shfl_xor_sync(0xffffffffu, mx, 1));
                mx = fmaxf(mx, __shfl_xor_sync(0xffffffffu, mx, 2));
                if (q4 == 0) Red[r*2 + cw] = mx;
            }
        __syncthreads();

        // ---- exp, write P (tf32) to Ps, partial sums ----
        float alpha[2][2];
#pragma unroll
        for (int mt = 0; mt < 2; mt++)
#pragma unroll
            for (int i = 0; i < 2; i++) {
                int r = rw*32 + mt*16 + i*8 + g;
                float tm = fmaxf(Red[r*2], Red[r*2 + 1]);
                float mn = fmaxf(mrun[mt][i], tm);
                alpha[mt][i] = __expf(mrun[mt][i] - mn);
                mrun[mt][i] = mn;
                float ssum = 0.0f;
#pragma unroll
                for (int nt = 0; nt < 4; nt++) {
                    float p0 = __expf(sfr[mt][nt][2*i]   - mn);
                    float p1 = __expf(sfr[mt][nt][2*i+1] - mn);
                    ssum += p0 + p1;
                    int col = cw*32 + nt*8 + 2*q4;
                    Ps[r*FPAD + col]     = to_tf32(p0);
                    Ps[r*FPAD + col + 1] = to_tf32(p1);
                }
                ssum += __shfl_xor_sync(0xffffffffu, ssum, 1);
                ssum += __shfl_xor_sync(0xffffffffu, ssum, 2);
                if (q4 == 0) Red[256 + r*2 + cw] = ssum;
            }
        __syncthreads();

        // ---- combine sums, rescale O ----
#pragma unroll
        for (int mt = 0; mt < 2; mt++)
#pragma unroll
            for (int i = 0; i < 2; i++) {
                int r = rw*32 + mt*16 + i*8 + g;
                float ts = Red[256 + r*2] + Red[256 + r*2 + 1];
                lrun[mt][i] = lrun[mt][i] * alpha[mt][i] + ts;
#pragma unroll
                for (int nt = 0; nt < 4; nt++) {
                    o[mt][nt][2*i]   *= alpha[mt][i];
                    o[mt][nt][2*i+1] *= alpha[mt][i];
                }
            }

        // ---- O += P @ V, warp tile 32 rows x 32 d-cols ----
#pragma unroll
        for (int s = 0; s < 8; s++) {
            unsigned pa[2][4];
#pragma unroll
            for (int mt = 0; mt < 2; mt++) {
                int row = rw*32 + mt*16 + g;
                int col = s*8 + q4;
                pa[mt][0] = __float_as_uint(Ps[row*FPAD + col]);
                pa[mt][1] = __float_as_uint(Ps[(row+8)*FPAD + col]);
                pa[mt][2] = __float_as_uint(Ps[row*FPAD + col + 4]);
                pa[mt][3] = __float_as_uint(Ps[(row+8)*FPAD + col + 4]);
            }
            unsigned vb[4][2];
#pragma unroll
            for (int nt = 0; nt < 4; nt++) {
                int d0 = cw*32 + nt*8 + g;
                vb[nt][0] = __float_as_uint(Vs[d0*FPAD + s*8 + q4]);
                vb[nt][1] = __float_as_uint(Vs[d0*FPAD + s*8 + 4 + q4]);
            }
#pragma unroll
            for (int mt = 0; mt < 2; mt++)
#pragma unroll
                for (int nt = 0; nt < 4; nt++)
                    mma_tf32(o[mt][nt], pa[mt], vb[nt]);
        }
    }

    // ---- epilogue: scale by 1/l, write O ----
#pragma unroll
    for (int mt = 0; mt < 2; mt++)
#pragma unroll
        for (int i = 0; i < 2; i++) {
            int r = rw*32 + mt*16 + i*8 + g;
            float inv = 1.0f / lrun[mt][i];
            size_t rowbase = ((size_t)b*Sq + qb*128 + r) * 1024 + h*64;
#pragma unroll
            for (int nt = 0; nt < 4; nt++) {
                int col = cw*32 + nt*8 + 2*q4;
                float2 o2 = make_float2(o[mt][nt][2*i] * inv, o[mt][nt][2*i+1] * inv);
                *(float2*)(Og + rowbase + col) = o2;
            }
        }
}

// ---------------- launch ----------------
extern "C" void kernel_launch(void* const* d_in, const int* in_sizes, int n_in,
                              void* d_out, int out_size) {
    (void)in_sizes; (void)n_in; (void)out_size;
    const float* h    = (const float*)d_in[0];
    const float* Wdkv = (const float*)d_in[1];
    const float* bdkv = (const float*)d_in[2];
    const float* Wdq  = (const float*)d_in[3];
    const float* bdq  = (const float*)d_in[4];
    const float* Wuk  = (const float*)d_in[5];
    const float* buk  = (const float*)d_in[6];
    const float* Wuv  = (const float*)d_in[7];
    const float* buv  = (const float*)d_in[8];
    const float* Wuq  = (const float*)d_in[9];
    const float* buq  = (const float*)d_in[10];
    const float* Wqr  = (const float*)d_in[11];
    const float* bqr  = (const float*)d_in[12];
    const float* Wkr  = (const float*)d_in[13];
    const float* bkr  = (const float*)d_in[14];
    const float* Wo   = (const float*)d_in[15];
    const float* bo   = (const float*)d_in[16];
    float* out = (float*)d_out;

    float *T1, *T2, *Q, *K, *V, *O, *Wc1, *bc1, *Wc2, *bc2;
    cudaGetSymbolAddress((void**)&T1,  g_T1);
    cudaGetSymbolAddress((void**)&T2,  g_T2);
    cudaGetSymbolAddress((void**)&Q,   g_Q);
    cudaGetSymbolAddress((void**)&K,   g_K);
    cudaGetSymbolAddress((void**)&V,   g_V);
    cudaGetSymbolAddress((void**)&O,   g_O);
    cudaGetSymbolAddress((void**)&Wc1, g_Wc1);
    cudaGetSymbolAddress((void**)&bc1, g_bc1);
    cudaGetSymbolAddress((void**)&Wc2, g_Wc2);
    cudaGetSymbolAddress((void**)&bc2, g_bc2);

    static int smem_set = 0;
    if (!smem_set) {
        cudaFuncSetAttribute(flash_tf32, cudaFuncAttributeMaxDynamicSharedMemorySize,
                             FLASH_SMEM_FLOATS * (int)sizeof(float));
        smem_set = 1;
    }

    // 1) pack weights
    pack1_kernel<<<(1024*512 + 255)/256, 256>>>(Wdkv, bdkv, Wdq, bdq, Wkr, bkr);
    pack2_kernel<<<(128*2816 + 255)/256, 256>>>(Wuk, buk, Wuv, buv, Wuq, buq, Wqr, bqr);

    // 2) down-proj + k_rot raw: [4096,1024] @ [1024,512] -> T1
    sgemm128<<<dim3(512/128, BS/128), 256>>>(h, Dm, Wc1, 512, bc1, T1, 512, Dm);

    // 3) up-projections (K=128)
    sgemm128<<<dim3(1792/128, BS/128), 256>>>(T1, 512, Wc2, 2816, bc2, T2, 2816, 128);
    sgemm128<<<dim3(1024/128, BS/128), 256>>>(T1 + 128, 512, Wc2 + 1792, 2816,
                                              bc2 + 1792, T2 + 1792, 2816, 128);

    // 4) rope + layout (tf32-rounds Q,K,V)
    assemble_qkv<<<BS, 256>>>(T1, T2, Q, K, V);

    // 5) attention (tf32 tensor cores)
    flash_tf32<<<dim3(Sq/128, Hh, Bsz), 256, FLASH_SMEM_FLOATS * sizeof(float)>>>(Q, K, V, O);

    // 6) output projection: [4096,1024] @ [1024,1024] + b_o -> out (fp32 exact)
    sgemm128<<<dim3(1024/128, BS/128), 256>>>(O, 1024, Wo, 1024, bo, out, 1024, Dm);
}